// round 2
// baseline (speedup 1.0000x reference)
#include <cuda_runtime.h>
#include <cstdint>

// Problem constants (fixed shapes from reference setup_inputs)
#define B   32
#define H   384
#define W   640
#define C   128
#define HS  96      // H / SCALE
#define WS  160     // W / SCALE
#define FW  30
#define THRESH 0.015f
#define TOPK 2000

// Static device scratch (allocation-free rule: __device__ globals are allowed)
__device__ float d_hwc[(size_t)B * HS * WS * C];   // transposed featmap (only needed rows valid)
__device__ int   d_idx[B * TOPK];                  // selected linear pixel indices, -1 = invalid
__device__ int   d_needed[B * HS];                 // per-batch row flags for transpose

// ---------------------------------------------------------------------------
// Kernel 1: ordered selection.
// One block per batch. Scans rows in order, block-wide compaction via ballot +
// warp scan; collects the first TOPK masked linear indices in ascending order.
// Also writes pts output directly and marks which feat rows the gather needs.
// r_shape may be int32 or int64-packed; sniff the layout at runtime.
// ---------------------------------------------------------------------------
__global__ __launch_bounds__(1024) void select_kernel(
    const float* __restrict__ prob,
    const float* __restrict__ ratio,
    const int* __restrict__ rshape_raw,
    float* __restrict__ pts_out)
{
    const int b   = blockIdx.x;
    const int tid = threadIdx.x;
    const int warp = tid >> 5;
    const int lane = tid & 31;

    // zero row flags for this batch
    if (tid < HS) d_needed[b * HS + tid] = 0;

    __shared__ int sWarpCnt[32];
    __shared__ int sWarpOff[32];
    __shared__ int sBase;
    __shared__ int sTotal;
    if (tid == 0) sBase = 0;

    // Dtype sniff: int64 little-endian packing -> rshape_raw[1] is the high
    // word of the first value (H=384 fits in 32 bits, so it is 0).
    // int32 packing -> rshape_raw[1] == W (640), nonzero.
    const int stride = (rshape_raw[1] == 0) ? 2 : 1;
    const int r0 = rshape_raw[(2 * b)     * stride];
    const int r1 = rshape_raw[(2 * b + 1) * stride];
    const int rowEnd = r0 - FW;   // exclusive
    const int colEnd = r1 - FW;   // exclusive
    const float rv = ratio[b];
    const float* pb = prob + (size_t)b * H * W;

    __syncthreads();

    for (int r = FW; r < rowEnd; ++r) {
        for (int cb = FW; cb < colEnd; cb += 1024) {
            const int c = cb + tid;
            const bool pred = (c < colEnd) && (pb[(size_t)r * W + c] > THRESH);
            const unsigned m = __ballot_sync(0xffffffffu, pred);
            if (lane == 0) sWarpCnt[warp] = __popc(m);
            __syncthreads();
            if (tid < 32) {
                int v = sWarpCnt[tid];
                int x = v;
                #pragma unroll
                for (int d = 1; d < 32; d <<= 1) {
                    int y = __shfl_up_sync(0xffffffffu, x, d);
                    if (tid >= d) x += y;
                }
                sWarpOff[tid] = x - v;          // exclusive prefix
                if (tid == 31) sTotal = x;      // inclusive total
            }
            __syncthreads();
            if (pred) {
                const int pos = sBase + sWarpOff[warp] + __popc(m & ((1u << lane) - 1u));
                if (pos < TOPK) {
                    const int lin = r * W + c;
                    d_idx[b * TOPK + pos] = lin;
                    pts_out[((size_t)b * TOPK + pos) * 2 + 0] = (float)c / rv;
                    pts_out[((size_t)b * TOPK + pos) * 2 + 1] = (float)r / rv;
                    const int ys = r >> 2;                       // floor(r/4)
                    d_needed[b * HS + ys] = 1;
                    const int ys1 = (ys + 1 < HS) ? (ys + 1) : (HS - 1);
                    d_needed[b * HS + ys1] = 1;
                }
            }
            __syncthreads();
            if (tid == 0) sBase += sTotal;
            __syncthreads();
            if (sBase >= TOPK) goto fill_tail;   // uniform branch (after sync)
        }
    }
fill_tail:
    __syncthreads();
    {
        const int base = (sBase < TOPK) ? sBase : TOPK;
        for (int k = base + tid; k < TOPK; k += 1024) {
            d_idx[b * TOPK + k] = -1;
            pts_out[((size_t)b * TOPK + k) * 2 + 0] = 0.0f;
            pts_out[((size_t)b * TOPK + k) * 2 + 1] = 0.0f;
        }
    }
}

// ---------------------------------------------------------------------------
// Kernel 2: CHW -> HWC transpose of only the needed rows.
// grid = (xtiles*ctiles, HS, B), block = (32, 8). Classic smem-tiled transpose.
// Blocks for rows not needed exit immediately.
// ---------------------------------------------------------------------------
__global__ __launch_bounds__(256) void transpose_kernel(const float* __restrict__ feat)
{
    const int b = blockIdx.z;
    const int y = blockIdx.y;
    if (!d_needed[b * HS + y]) return;

    const int xt = blockIdx.x % (WS / 32);   // 0..4
    const int ct = blockIdx.x / (WS / 32);   // 0..3

    __shared__ float tile[32][33];
    const int tx = threadIdx.x;  // 0..31
    const int ty = threadIdx.y;  // 0..7

    const float* src = feat + ((size_t)b * C) * (HS * WS) + (size_t)y * WS;
    #pragma unroll
    for (int i = 0; i < 4; ++i) {
        const int cc = ct * 32 + ty + i * 8;
        tile[ty + i * 8][tx] = src[(size_t)cc * (HS * WS) + xt * 32 + tx];
    }
    __syncthreads();
    float* dst = d_hwc + ((size_t)(b * HS + y) * WS) * C;
    #pragma unroll
    for (int i = 0; i < 4; ++i) {
        const int x = xt * 32 + ty + i * 8;
        dst[(size_t)x * C + ct * 32 + tx] = tile[tx][ty + i * 8];
    }
}

// ---------------------------------------------------------------------------
// Kernel 3: bilinear gather from HWC scratch.
// grid = (TOPK/16, B), block = 128 (one thread per channel).
// All taps are coalesced 512B channel vectors; output writes fully coalesced.
// ---------------------------------------------------------------------------
__global__ __launch_bounds__(128) void gather_kernel(float* __restrict__ des_out)
{
    const int b  = blockIdx.y;
    const int p0 = blockIdx.x * 16;
    const int c  = threadIdx.x;

    #pragma unroll 4
    for (int i = 0; i < 16; ++i) {
        const int p = p0 + i;
        const int lin = d_idx[b * TOPK + p];
        float v = 0.0f;
        if (lin >= 0) {
            const int y = lin / W;
            const int x = lin - y * W;
            const int x0 = x >> 2;
            const int y0 = y >> 2;
            const float fx = (float)(x & 3) * 0.25f;
            const float fy = (float)(y & 3) * 0.25f;
            const float* base = d_hwc + (((size_t)(b * HS + y0) * WS + x0) * C) + c;
            const float Ia = base[0];            // (y0, x0)
            const float Ic = base[C];            // (y0, x1)
            const float Ib = base[(size_t)WS * C];       // (y1, x0)
            const float Id = base[(size_t)WS * C + C];   // (y1, x1)
            const float wa = (1.0f - fx) * (1.0f - fy);
            const float wb = (1.0f - fx) * fy;
            const float wc = fx * (1.0f - fy);
            const float wd = fx * fy;
            v = Ia * wa + Ib * wb + Ic * wc + Id * wd;
        }
        des_out[((size_t)b * TOPK + p) * (size_t)C + c] = v;
    }
}

// ---------------------------------------------------------------------------
extern "C" void kernel_launch(void* const* d_in, const int* in_sizes, int n_in,
                              void* d_out, int out_size)
{
    const float* prob   = (const float*)d_in[0];      // [B,1,H,W]
    const float* feat   = (const float*)d_in[1];      // [B,C,HS,WS]
    const float* ratio  = (const float*)d_in[2];      // [B,1]
    const int*   rshape = (const int*)d_in[3];        // [B,2] int32 (or int64-packed)

    float* pts_out = (float*)d_out;                        // [B,TOPK,2]
    float* des_out = (float*)d_out + (size_t)B * TOPK * 2; // [B,TOPK,C]

    select_kernel<<<B, 1024>>>(prob, ratio, rshape, pts_out);
    transpose_kernel<<<dim3((WS / 32) * (C / 32), HS, B), dim3(32, 8)>>>(feat);
    gather_kernel<<<dim3(TOPK / 16, B), 128>>>(des_out);
}

// round 3
// speedup vs baseline: 2.2321x; 2.2321x over previous
#include <cuda_runtime.h>
#include <cstdint>

#define B   32
#define H   384
#define W   640
#define C   128
#define HS  96      // H / SCALE
#define WS  160     // W / SCALE
#define FW  30
#define THRESH 0.015f
#define TOPK 2000
#define TBLOCKS 2048   // persistent transpose grid

// Static device scratch (allocation-free rule: __device__ globals allowed)
__device__ float d_hwc[(size_t)B * HS * WS * C];   // transposed featmap (only needed rows valid)
__device__ int   d_idx[B * TOPK];                  // selected linear pixel indices, -1 = invalid
__device__ int   d_ymin[B];                        // first needed feat row per batch
__device__ int   d_nrows[B];                       // number of needed feat rows per batch

// ---------------------------------------------------------------------------
// Kernel 1: ordered selection. One block per batch. Block-wide ordered stream
// compaction (ballot + warp scan) over the in-region thresholded prob map;
// early-exits after TOPK hits. Writes pts directly; records the contiguous
// feat-row range needed by the bilinear gather.
// ---------------------------------------------------------------------------
__global__ __launch_bounds__(1024) void select_kernel(
    const float* __restrict__ prob,
    const float* __restrict__ ratio,
    const int* __restrict__ rshape_raw,
    float* __restrict__ pts_out)
{
    const int b    = blockIdx.x;
    const int tid  = threadIdx.x;
    const int warp = tid >> 5;
    const int lane = tid & 31;

    __shared__ int sWarpCnt[32];
    __shared__ int sWarpOff[32];
    __shared__ int sBase;
    __shared__ int sTotal;
    __shared__ int sRmin, sRmax;
    if (tid == 0) { sBase = 0; sRmin = 0x7fffffff; sRmax = -1; }

    // r_shape dtype sniff: int64 little-endian -> word 1 is the high half of
    // the first value (0, since H fits in 32 bits); int32 -> word 1 is W != 0.
    const int stride = (rshape_raw[1] == 0) ? 2 : 1;
    const int r0 = rshape_raw[(2 * b)     * stride];
    const int r1 = rshape_raw[(2 * b + 1) * stride];
    const int rowEnd = r0 - FW;   // exclusive
    const int colEnd = r1 - FW;   // exclusive
    const float rv = ratio[b];
    const float* pb = prob + (size_t)b * H * W;

    __syncthreads();

    for (int r = FW; r < rowEnd; ++r) {
        for (int cb = FW; cb < colEnd; cb += 1024) {
            const int c = cb + tid;
            const bool pred = (c < colEnd) && (pb[(size_t)r * W + c] > THRESH);
            const unsigned m = __ballot_sync(0xffffffffu, pred);
            if (lane == 0) sWarpCnt[warp] = __popc(m);
            __syncthreads();
            if (tid < 32) {
                int v = sWarpCnt[tid];
                int x = v;
                #pragma unroll
                for (int d = 1; d < 32; d <<= 1) {
                    int y = __shfl_up_sync(0xffffffffu, x, d);
                    if (tid >= d) x += y;
                }
                sWarpOff[tid] = x - v;          // exclusive prefix
                if (tid == 31) sTotal = x;      // inclusive total
            }
            __syncthreads();
            if (pred) {
                const int pos = sBase + sWarpOff[warp] + __popc(m & ((1u << lane) - 1u));
                if (pos < TOPK) {
                    d_idx[b * TOPK + pos] = r * W + c;
                    pts_out[((size_t)b * TOPK + pos) * 2 + 0] = (float)c / rv;
                    pts_out[((size_t)b * TOPK + pos) * 2 + 1] = (float)r / rv;
                }
            }
            __syncthreads();
            if (tid == 0) {
                if (sTotal > 0 && sBase < TOPK) {
                    if (r < sRmin) sRmin = r;
                    sRmax = r;
                }
                sBase += sTotal;
            }
            __syncthreads();
            if (sBase >= TOPK) goto fill_tail;
        }
    }
fill_tail:
    __syncthreads();
    {
        const int base = (sBase < TOPK) ? sBase : TOPK;
        for (int k = base + tid; k < TOPK; k += 1024) {
            d_idx[b * TOPK + k] = -1;
            pts_out[((size_t)b * TOPK + k) * 2 + 0] = 0.0f;
            pts_out[((size_t)b * TOPK + k) * 2 + 1] = 0.0f;
        }
        if (tid == 0) {
            if (sRmax < 0) {
                d_ymin[b] = 0; d_nrows[b] = 0;
            } else {
                int ymin = sRmin >> 2;                                // floor tap row
                int ymax = (sRmax >> 2) + 1;                          // +1 tap row
                if (ymax > HS - 1) ymax = HS - 1;
                d_ymin[b] = ymin;
                d_nrows[b] = ymax - ymin + 1;
            }
        }
    }
}

// ---------------------------------------------------------------------------
// Kernel 2: persistent CHW -> HWC transpose over a compact task list.
// Task = (batch, feat row, tile); 20 tiles per row (5 x-tiles * 4 c-tiles).
// Each block computes the 32-batch prefix (trivial), then strides tasks.
// ---------------------------------------------------------------------------
__global__ __launch_bounds__(256) void transpose_kernel(const float* __restrict__ feat)
{
    __shared__ int sOff[B + 1];
    __shared__ int sYmin[B];
    __shared__ float tile[32][33];

    const int t0 = threadIdx.y * 32 + threadIdx.x;
    if (t0 == 0) {
        int acc = 0;
        #pragma unroll
        for (int b = 0; b < B; ++b) {
            sOff[b] = acc;
            sYmin[b] = d_ymin[b];
            acc += d_nrows[b];
        }
        sOff[B] = acc;
    }
    __syncthreads();
    const int totalTasks = sOff[B] * 20;

    const int tx = threadIdx.x;  // 0..31
    const int ty = threadIdx.y;  // 0..7

    for (int t = blockIdx.x; t < totalTasks; t += TBLOCKS) {
        const int rowTask = t / 20;
        const int tileId  = t - rowTask * 20;
        int b = 0;
        while (sOff[b + 1] <= rowTask) ++b;        // uniform across block
        const int y  = sYmin[b] + (rowTask - sOff[b]);
        const int xt = tileId % 5;                 // 0..4 (x tiles of 32)
        const int ct = tileId / 5;                 // 0..3 (c tiles of 32)

        const float* src = feat + ((size_t)b * C) * (HS * WS) + (size_t)y * WS;
        #pragma unroll
        for (int i = 0; i < 4; ++i) {
            const int cc = ct * 32 + ty + i * 8;
            tile[ty + i * 8][tx] = src[(size_t)cc * (HS * WS) + xt * 32 + tx];
        }
        __syncthreads();
        float* dst = d_hwc + ((size_t)(b * HS + y) * WS) * C;
        #pragma unroll
        for (int i = 0; i < 4; ++i) {
            const int x = xt * 32 + ty + i * 8;
            dst[(size_t)x * C + ct * 32 + tx] = tile[tx][ty + i * 8];
        }
        __syncthreads();
    }
}

// ---------------------------------------------------------------------------
// Kernel 3: bilinear gather, vectorized float4.
// Block = 128 threads: 32 channel-groups (4 ch each) x 4 point-lanes.
// 16 points per block; indices staged in smem. All taps LDG.128, out STG.128.
// ---------------------------------------------------------------------------
__global__ __launch_bounds__(128) void gather_kernel(float* __restrict__ des_out)
{
    const int b  = blockIdx.y;
    const int p0 = blockIdx.x * 16;
    const int cg = threadIdx.x & 31;   // channel group -> channels 4*cg..4*cg+3
    const int pl = threadIdx.x >> 5;   // point lane 0..3

    __shared__ int sIdx[16];
    if (threadIdx.x < 16) sIdx[threadIdx.x] = d_idx[b * TOPK + p0 + threadIdx.x];
    __syncthreads();

    #pragma unroll
    for (int i = 0; i < 4; ++i) {
        const int p = p0 + pl + i * 4;
        const int lin = sIdx[pl + i * 4];
        float4 v = make_float4(0.f, 0.f, 0.f, 0.f);
        if (lin >= 0) {
            const int y = lin / W;
            const int x = lin - y * W;
            const int x0 = x >> 2;
            const int y0 = y >> 2;
            const float fx = (float)(x & 3) * 0.25f;
            const float fy = (float)(y & 3) * 0.25f;
            const float4* base = (const float4*)(d_hwc +
                (((size_t)(b * HS + y0) * WS + x0) * C)) + cg;
            const float4 Ia = base[0];                 // (y0, x0)
            const float4 Ic = base[C / 4];             // (y0, x1)
            const float4 Ib = base[(size_t)WS * C / 4];        // (y1, x0)
            const float4 Id = base[(size_t)WS * C / 4 + C / 4];// (y1, x1)
            const float wa = (1.0f - fx) * (1.0f - fy);
            const float wb = (1.0f - fx) * fy;
            const float wc = fx * (1.0f - fy);
            const float wd = fx * fy;
            v.x = Ia.x * wa + Ib.x * wb + Ic.x * wc + Id.x * wd;
            v.y = Ia.y * wa + Ib.y * wb + Ic.y * wc + Id.y * wd;
            v.z = Ia.z * wa + Ib.z * wb + Ic.z * wc + Id.z * wd;
            v.w = Ia.w * wa + Ib.w * wb + Ic.w * wc + Id.w * wd;
        }
        ((float4*)des_out)[((size_t)b * TOPK + p) * (C / 4) + cg] = v;
    }
}

// ---------------------------------------------------------------------------
extern "C" void kernel_launch(void* const* d_in, const int* in_sizes, int n_in,
                              void* d_out, int out_size)
{
    const float* prob   = (const float*)d_in[0];      // [B,1,H,W]
    const float* feat   = (const float*)d_in[1];      // [B,C,HS,WS]
    const float* ratio  = (const float*)d_in[2];      // [B,1]
    const int*   rshape = (const int*)d_in[3];        // [B,2] int32 (or int64-packed)

    float* pts_out = (float*)d_out;                        // [B,TOPK,2]
    float* des_out = (float*)d_out + (size_t)B * TOPK * 2; // [B,TOPK,C]

    select_kernel<<<B, 1024>>>(prob, ratio, rshape, pts_out);
    transpose_kernel<<<TBLOCKS, dim3(32, 8)>>>(feat);
    gather_kernel<<<dim3(TOPK / 16, B), 128>>>(des_out);
}

// round 4
// speedup vs baseline: 2.4373x; 1.0919x over previous
#include <cuda_runtime.h>
#include <cstdint>

#define B   32
#define H   384
#define W   640
#define C   128
#define HS  96      // H / SCALE
#define WS  160     // W / SCALE
#define FW  30
#define THRESH 0.015f
#define TOPK 2000
#define TBLOCKS 2048   // persistent transpose grid
#define PIX 4          // pixels per thread per swath in select

// Static device scratch (allocation-free rule: __device__ globals allowed)
__device__ float d_hwc[(size_t)B * HS * WS * C];   // transposed featmap (only needed rows valid)
__device__ int   d_idx[B * TOPK];                  // selected linear pixel indices, -1 = invalid
__device__ int   d_ymin[B];                        // first needed feat row per batch
__device__ int   d_nrows[B];                       // number of needed feat rows per batch

// ---------------------------------------------------------------------------
// Kernel 1: ordered selection, swath-parallel.
// One block per batch. The in-region pixel stream (row-major, cols FW..colEnd)
// is split into swaths of 1024*PIX pixels; thread t owns PIX consecutive
// pixels. All loads of a swath issue together (MLP=PIX per thread, no
// serialization), then ONE block scan of per-thread popcounts assigns ordered
// output positions. At ~98.5% density one swath covers TOPK.
// ---------------------------------------------------------------------------
__global__ __launch_bounds__(1024) void select_kernel(
    const float* __restrict__ prob,
    const float* __restrict__ ratio,
    const int* __restrict__ rshape_raw,
    float* __restrict__ pts_out)
{
    const int b    = blockIdx.x;
    const int tid  = threadIdx.x;
    const int warp = tid >> 5;
    const int lane = tid & 31;

    __shared__ int sWarpBase[32];   // exclusive warp offsets
    __shared__ int sTotal;          // block total this swath
    __shared__ int sBase;
    __shared__ int sRmin, sRmax;
    if (tid == 0) { sBase = 0; sRmin = 0x7fffffff; sRmax = -1; }

    // r_shape dtype sniff: int64 LE -> word 1 is high half of first value (0);
    // int32 -> word 1 is W != 0.
    const int stride = (rshape_raw[1] == 0) ? 2 : 1;
    const int r0 = rshape_raw[(2 * b)     * stride];
    const int r1 = rshape_raw[(2 * b + 1) * stride];
    const int rowW     = r1 - 2 * FW;              // valid cols per row
    const int totalPix = (r0 - 2 * FW) * rowW;     // in-region pixel count
    const float rv = ratio[b];
    const float* pb = prob + (size_t)b * H * W;

    __syncthreads();

    for (int sw = 0; sw < totalPix; sw += 1024 * PIX) {
        const int pix0 = sw + PIX * tid;
        const int rq = (rowW > 0) ? pix0 / rowW : 0;
        int rStart = FW + rq;
        int cStart = FW + pix0 - rq * rowW;

        unsigned pmask = 0;
        int rr[PIX], cc[PIX];
        {
            int ri = rStart, ci = cStart;
            #pragma unroll
            for (int j = 0; j < PIX; ++j) {
                rr[j] = ri; cc[j] = ci;
                if ((pix0 + j) < totalPix) {
                    if (pb[(size_t)ri * W + ci] > THRESH) pmask |= (1u << j);
                }
                if (++ci >= FW + rowW) { ci = FW; ++ri; }
            }
        }
        const int cnt = __popc(pmask);

        // block exclusive scan of per-thread cnt
        int incl = cnt;
        #pragma unroll
        for (int d = 1; d < 32; d <<= 1) {
            int y = __shfl_up_sync(0xffffffffu, incl, d);
            if (lane >= d) incl += y;
        }
        if (lane == 31) sWarpBase[warp] = incl;    // warp totals
        __syncthreads();
        if (tid < 32) {
            int v = sWarpBase[tid];
            int x = v;
            #pragma unroll
            for (int d = 1; d < 32; d <<= 1) {
                int y = __shfl_up_sync(0xffffffffu, x, d);
                if (tid >= d) x += y;
            }
            sWarpBase[tid] = x - v;                // exclusive warp base
            if (tid == 31) sTotal = x;             // block total
        }
        __syncthreads();
        int pos = sBase + sWarpBase[warp] + (incl - cnt);

        int myRmin = 0x7fffffff, myRmax = -1;
        #pragma unroll
        for (int j = 0; j < PIX; ++j) {
            if (pmask & (1u << j)) {
                if (pos < TOPK) {
                    d_idx[b * TOPK + pos] = rr[j] * W + cc[j];
                    ((float2*)pts_out)[(size_t)b * TOPK + pos] =
                        make_float2((float)cc[j] / rv, (float)rr[j] / rv);
                    if (rr[j] < myRmin) myRmin = rr[j];
                    if (rr[j] > myRmax) myRmax = rr[j];
                }
                ++pos;
            }
        }
        if (myRmax >= 0) {
            atomicMin(&sRmin, myRmin);
            atomicMax(&sRmax, myRmax);
        }
        __syncthreads();
        if (tid == 0) sBase += sTotal;
        __syncthreads();
        if (sBase >= TOPK) break;
    }

    __syncthreads();
    {
        const int base = (sBase < TOPK) ? sBase : TOPK;
        for (int k = base + tid; k < TOPK; k += 1024) {
            d_idx[b * TOPK + k] = -1;
            ((float2*)pts_out)[(size_t)b * TOPK + k] = make_float2(0.0f, 0.0f);
        }
        if (tid == 0) {
            if (sRmax < 0) {
                d_ymin[b] = 0; d_nrows[b] = 0;
            } else {
                int ymin = sRmin >> 2;
                int ymax = (sRmax >> 2) + 1;
                if (ymax > HS - 1) ymax = HS - 1;
                d_ymin[b] = ymin;
                d_nrows[b] = ymax - ymin + 1;
            }
        }
    }
}

// ---------------------------------------------------------------------------
// Kernel 2: persistent CHW -> HWC transpose over a compact task list.
// Task = (batch, feat row, tile); 20 tiles per row (5 x-tiles * 4 c-tiles).
// ---------------------------------------------------------------------------
__global__ __launch_bounds__(256) void transpose_kernel(const float* __restrict__ feat)
{
    __shared__ int sOff[B + 1];
    __shared__ int sYmin[B];
    __shared__ float tile[32][33];

    const int t0 = threadIdx.y * 32 + threadIdx.x;
    if (t0 == 0) {
        int acc = 0;
        #pragma unroll
        for (int b = 0; b < B; ++b) {
            sOff[b] = acc;
            sYmin[b] = d_ymin[b];
            acc += d_nrows[b];
        }
        sOff[B] = acc;
    }
    __syncthreads();
    const int totalTasks = sOff[B] * 20;

    const int tx = threadIdx.x;  // 0..31
    const int ty = threadIdx.y;  // 0..7

    for (int t = blockIdx.x; t < totalTasks; t += TBLOCKS) {
        const int rowTask = t / 20;
        const int tileId  = t - rowTask * 20;
        int b = 0;
        while (sOff[b + 1] <= rowTask) ++b;        // uniform across block
        const int y  = sYmin[b] + (rowTask - sOff[b]);
        const int xt = tileId % 5;                 // 0..4 (x tiles of 32)
        const int ct = tileId / 5;                 // 0..3 (c tiles of 32)

        const float* src = feat + ((size_t)b * C) * (HS * WS) + (size_t)y * WS;
        #pragma unroll
        for (int i = 0; i < 4; ++i) {
            const int cc = ct * 32 + ty + i * 8;
            tile[ty + i * 8][tx] = src[(size_t)cc * (HS * WS) + xt * 32 + tx];
        }
        __syncthreads();
        float* dst = d_hwc + ((size_t)(b * HS + y) * WS) * C;
        #pragma unroll
        for (int i = 0; i < 4; ++i) {
            const int x = xt * 32 + ty + i * 8;
            dst[(size_t)x * C + ct * 32 + tx] = tile[tx][ty + i * 8];
        }
        __syncthreads();
    }
}

// ---------------------------------------------------------------------------
// Kernel 3: bilinear gather, vectorized float4.
// Block = 128 threads: 32 channel-groups (4 ch each) x 4 point-lanes.
// ---------------------------------------------------------------------------
__global__ __launch_bounds__(128) void gather_kernel(float* __restrict__ des_out)
{
    const int b  = blockIdx.y;
    const int p0 = blockIdx.x * 16;
    const int cg = threadIdx.x & 31;   // channel group -> channels 4*cg..4*cg+3
    const int pl = threadIdx.x >> 5;   // point lane 0..3

    __shared__ int sIdx[16];
    if (threadIdx.x < 16) sIdx[threadIdx.x] = d_idx[b * TOPK + p0 + threadIdx.x];
    __syncthreads();

    #pragma unroll
    for (int i = 0; i < 4; ++i) {
        const int p = p0 + pl + i * 4;
        const int lin = sIdx[pl + i * 4];
        float4 v = make_float4(0.f, 0.f, 0.f, 0.f);
        if (lin >= 0) {
            const int y = lin / W;
            const int x = lin - y * W;
            const int x0 = x >> 2;
            const int y0 = y >> 2;
            const float fx = (float)(x & 3) * 0.25f;
            const float fy = (float)(y & 3) * 0.25f;
            const float4* base = (const float4*)(d_hwc +
                (((size_t)(b * HS + y0) * WS + x0) * C)) + cg;
            const float4 Ia = base[0];                 // (y0, x0)
            const float4 Ic = base[C / 4];             // (y0, x1)
            const float4 Ib = base[(size_t)WS * C / 4];        // (y1, x0)
            const float4 Id = base[(size_t)WS * C / 4 + C / 4];// (y1, x1)
            const float wa = (1.0f - fx) * (1.0f - fy);
            const float wb = (1.0f - fx) * fy;
            const float wc = fx * (1.0f - fy);
            const float wd = fx * fy;
            v.x = Ia.x * wa + Ib.x * wb + Ic.x * wc + Id.x * wd;
            v.y = Ia.y * wa + Ib.y * wb + Ic.y * wc + Id.y * wd;
            v.z = Ia.z * wa + Ib.z * wb + Ic.z * wc + Id.z * wd;
            v.w = Ia.w * wa + Ib.w * wb + Ic.w * wc + Id.w * wd;
        }
        ((float4*)des_out)[((size_t)b * TOPK + p) * (C / 4) + cg] = v;
    }
}

// ---------------------------------------------------------------------------
extern "C" void kernel_launch(void* const* d_in, const int* in_sizes, int n_in,
                              void* d_out, int out_size)
{
    const float* prob   = (const float*)d_in[0];      // [B,1,H,W]
    const float* feat   = (const float*)d_in[1];      // [B,C,HS,WS]
    const float* ratio  = (const float*)d_in[2];      // [B,1]
    const int*   rshape = (const int*)d_in[3];        // [B,2] int32 (or int64-packed)

    float* pts_out = (float*)d_out;                        // [B,TOPK,2]
    float* des_out = (float*)d_out + (size_t)B * TOPK * 2; // [B,TOPK,C]

    select_kernel<<<B, 1024>>>(prob, ratio, rshape, pts_out);
    transpose_kernel<<<TBLOCKS, dim3(32, 8)>>>(feat);
    gather_kernel<<<dim3(TOPK / 16, B), 128>>>(des_out);
}